// round 2
// baseline (speedup 1.0000x reference)
#include <cuda_runtime.h>
#include <math.h>

#define EDIM 128
#define HDIM 128
#define LSEQ 10
#define NPOS 10
#define NNEG 50
#define NB   61
#define NG   384

// Scratch: final hidden state per chain (61 x 128).
__device__ float g_enc[NB * HDIM];

// ---------------------------------------------------------------------------
// Kernel 1: one CTA per chain. 384 threads; thread g owns weight row g in
// registers (32 x float4). Computes gi for all 10 steps, then runs the GRU
// recurrence with 2 barriers per step. Threads 0..127 write enc[b].
// ---------------------------------------------------------------------------
__global__ __launch_bounds__(NG, 1) void enc_kernel(
    const int* __restrict__ phr, const int* __restrict__ pos,
    const int* __restrict__ neg,
    const float* __restrict__ u_emb, const float* __restrict__ v_emb,
    const float* __restrict__ w_ih, const float* __restrict__ w_hh,
    const float* __restrict__ b_ih, const float* __restrict__ b_hh,
    const float* __restrict__ h0)
{
    __shared__ float sx[LSEQ][EDIM];   // gathered embeddings
    __shared__ float sgi[LSEQ][NG];    // input-projection gates
    __shared__ float sgh[NG];          // recurrent gates (per step)
    __shared__ float sh[HDIM];         // hidden state

    const int b   = blockIdx.x;
    const int tid = threadIdx.x;

    // --- gather x[b] : 10 rows of 128 floats, float4-coalesced -------------
    if (tid < LSEQ * 32) {
        int t = tid >> 5, lane = tid & 31;
        int idx;
        const float* table;
        if (b == 0)            { idx = phr[t];                         table = u_emb; }
        else if (b <= NPOS)    { idx = pos[(b - 1) * LSEQ + t];        table = v_emb; }
        else                   { idx = neg[(b - 1 - NPOS) * LSEQ + t]; table = v_emb; }
        const float4* src = (const float4*)(table + (size_t)idx * EDIM);
        ((float4*)&sx[t][0])[lane] = src[lane];
    }
    if (tid < HDIM) sh[tid] = h0[tid];
    __syncthreads();

    const int g = tid;
    float4 wr[32];

    // --- input projection: gi[t][g] = dot(w_ih[g], x[t]) + b_ih[g] ---------
    {
        const float4* wp = (const float4*)(w_ih + (size_t)g * EDIM);
#pragma unroll
        for (int i = 0; i < 32; i++) wr[i] = wp[i];
    }
    const float bi = b_ih[g];
    const float bh = b_hh[g];

#pragma unroll
    for (int t = 0; t < LSEQ; t++) {
        const float4* xp = (const float4*)&sx[t][0];
        float a0 = 0.f, a1 = 0.f, a2 = 0.f, a3 = 0.f;
#pragma unroll
        for (int k = 0; k < 32; k++) {
            float4 xv = xp[k];
            a0 = fmaf(wr[k].x, xv.x, a0);
            a1 = fmaf(wr[k].y, xv.y, a1);
            a2 = fmaf(wr[k].z, xv.z, a2);
            a3 = fmaf(wr[k].w, xv.w, a3);
        }
        sgi[t][g] = (a0 + a1) + (a2 + a3) + bi;
    }

    // --- swap in recurrent weights -----------------------------------------
    {
        const float4* wp = (const float4*)(w_hh + (size_t)g * HDIM);
#pragma unroll
        for (int i = 0; i < 32; i++) wr[i] = wp[i];
    }
    __syncthreads();   // sgi + sh ready

    // --- recurrence ---------------------------------------------------------
    float hnew = 0.f;
#pragma unroll
    for (int t = 0; t < LSEQ; t++) {
        const float4* hp = (const float4*)sh;
        float a0 = 0.f, a1 = 0.f, a2 = 0.f, a3 = 0.f;
#pragma unroll
        for (int k = 0; k < 32; k++) {
            float4 hv = hp[k];
            a0 = fmaf(wr[k].x, hv.x, a0);
            a1 = fmaf(wr[k].y, hv.y, a1);
            a2 = fmaf(wr[k].z, hv.z, a2);
            a3 = fmaf(wr[k].w, hv.w, a3);
        }
        sgh[g] = (a0 + a1) + (a2 + a3) + bh;
        __syncthreads();   // gh done; all h reads of step t done

        if (g < HDIM) {
            float ir = sgi[t][g], iz = sgi[t][g + 128], in_ = sgi[t][g + 256];
            float hr = sgh[g],    hz = sgh[g + 128],    hn  = sgh[g + 256];
            float r = 1.f / (1.f + expf(-(ir + hr)));
            float z = 1.f / (1.f + expf(-(iz + hz)));
            float n = tanhf(in_ + r * hn);
            hnew = (1.f - z) * n + z * sh[g];
            sh[g] = hnew;            // only thread g touches sh[g] here
        }
        __syncthreads();   // new h visible before next matvec
    }

    if (g < HDIM) g_enc[b * HDIM + g] = hnew;
}

// ---------------------------------------------------------------------------
// Kernel 2: loss. 1 CTA, 32 warps; warp w handles enc rows {1+w, 33+w}.
// ---------------------------------------------------------------------------
__global__ __launch_bounds__(1024, 1) void loss_kernel(float* __restrict__ out)
{
    const int tid  = threadIdx.x;
    const int lane = tid & 31;
    const int w    = tid >> 5;

    float4 nd = ((const float4*)g_enc)[lane];   // node = enc[0]

    float pos_acc = 0.f, neg_sum = 0.f;
    for (int i = 1 + w; i <= NPOS + NNEG; i += 32) {
        float4 ev = ((const float4*)(g_enc + (size_t)i * HDIM))[lane];
        float p = nd.x * ev.x + nd.y * ev.y + nd.z * ev.z + nd.w * ev.w;
#pragma unroll
        for (int off = 16; off; off >>= 1)
            p += __shfl_xor_sync(0xffffffffu, p, off);
        float s = p * (1.0f / (float)HDIM);
        if (i <= NPOS) {
            pos_acc += s;
        } else if (s > 0.f) {
            neg_sum += expf(s);
        }
    }

    __shared__ float sp[32], sn[32];
    if (lane == 0) { sp[w] = pos_acc; sn[w] = neg_sum; }
    __syncthreads();
    if (tid == 0) {
        float P = 0.f, Ns = 0.f;
#pragma unroll
        for (int i = 0; i < 32; i++) { P += sp[i]; Ns += sn[i]; }
        // loss = -(neg_loss + pos_loss), neg_loss = -log(1+neg_sum)
        out[0] = log1pf(Ns) - P;
    }
}

// ---------------------------------------------------------------------------
extern "C" void kernel_launch(void* const* d_in, const int* in_sizes, int n_in,
                              void* d_out, int out_size)
{
    (void)in_sizes; (void)n_in; (void)out_size;
    enc_kernel<<<NB, NG>>>(
        (const int*)d_in[0], (const int*)d_in[1], (const int*)d_in[2],
        (const float*)d_in[3], (const float*)d_in[4],
        (const float*)d_in[5], (const float*)d_in[6],
        (const float*)d_in[7], (const float*)d_in[8],
        (const float*)d_in[9]);
    loss_kernel<<<1, 1024>>>((float*)d_out);
}

// round 3
// speedup vs baseline: 1.0021x; 1.0021x over previous
#include <cuda_runtime.h>
#include <math.h>

#define EDIM 128
#define HDIM 128
#define LSEQ 10
#define NPOS 10
#define NNEG 50
#define NB   61
#define NG   384

// Packed f32x2 FMA (Blackwell): d = a*b + c elementwise on 2 packed floats.
#define FMA_F32X2(d, a, b, c) \
    asm("fma.rn.f32x2 %0, %1, %2, %3;" : "=l"(d) : "l"(a), "l"(b), "l"(c))

__device__ __forceinline__ float unpack_sum(unsigned long long v) {
    float lo, hi;
    asm("mov.b64 {%0, %1}, %2;" : "=f"(lo), "=f"(hi) : "l"(v));
    return lo + hi;
}

// Scratch: final hidden state per chain (61 x 128) + completion counter.
__device__ float g_enc[NB * HDIM];
__device__ int   g_done;   // zero-initialized; last CTA resets it to 0

// ---------------------------------------------------------------------------
// One CTA per chain; thread g owns weight row g register-resident as packed
// f32x2 pairs. Last CTA to finish computes the loss (fused, single launch).
// ---------------------------------------------------------------------------
__global__ __launch_bounds__(NG, 1) void enc_loss_kernel(
    const int* __restrict__ phr, const int* __restrict__ pos,
    const int* __restrict__ neg,
    const float* __restrict__ u_emb, const float* __restrict__ v_emb,
    const float* __restrict__ w_ih, const float* __restrict__ w_hh,
    const float* __restrict__ b_ih, const float* __restrict__ b_hh,
    const float* __restrict__ h0, float* __restrict__ out)
{
    __shared__ float sx[LSEQ][EDIM];   // gathered embeddings
    __shared__ float sgi[LSEQ][NG];    // input-projection gates
    __shared__ float sgh[NG];          // recurrent gates (per step)
    __shared__ float sh[HDIM];         // hidden state
    __shared__ int   s_amlast;
    __shared__ float sp[12], sn[12];

    const int b    = blockIdx.x;
    const int tid  = threadIdx.x;
    const int lane = tid & 31;
    const int w    = tid >> 5;

    // --- gather x[b] : 10 rows of 128 floats, float4-coalesced -------------
    if (tid < LSEQ * 32) {
        int t = tid >> 5, l = tid & 31;
        int idx;
        const float* table;
        if (b == 0)            { idx = phr[t];                         table = u_emb; }
        else if (b <= NPOS)    { idx = pos[(b - 1) * LSEQ + t];        table = v_emb; }
        else                   { idx = neg[(b - 1 - NPOS) * LSEQ + t]; table = v_emb; }
        const float4* src = (const float4*)(table + (size_t)idx * EDIM);
        ((float4*)&sx[t][0])[l] = src[l];
    }
    if (tid < HDIM) sh[tid] = h0[tid];
    __syncthreads();

    const int g = tid;
    ulonglong2 wq[32];   // 128 floats as 64 packed f32x2 pairs

    // --- input projection: gi[t][g] = dot(w_ih[g], x[t]) + b_ih[g] ---------
    {
        const ulonglong2* wp = (const ulonglong2*)(w_ih + (size_t)g * EDIM);
#pragma unroll
        for (int i = 0; i < 32; i++) wq[i] = wp[i];
    }
    const float bi = b_ih[g];
    const float bh = b_hh[g];

#pragma unroll
    for (int t = 0; t < LSEQ; t++) {
        const ulonglong2* xp = (const ulonglong2*)&sx[t][0];
        unsigned long long a0 = 0ull, a1 = 0ull;   // two packed accumulators
#pragma unroll
        for (int k = 0; k < 32; k++) {
            ulonglong2 xv = xp[k];
            FMA_F32X2(a0, wq[k].x, xv.x, a0);
            FMA_F32X2(a1, wq[k].y, xv.y, a1);
        }
        sgi[t][g] = unpack_sum(a0) + unpack_sum(a1) + bi;
    }

    // --- swap in recurrent weights -----------------------------------------
    {
        const ulonglong2* wp = (const ulonglong2*)(w_hh + (size_t)g * HDIM);
#pragma unroll
        for (int i = 0; i < 32; i++) wq[i] = wp[i];
    }
    __syncthreads();   // sgi + sh ready

    // --- recurrence ---------------------------------------------------------
    float hnew = 0.f;
#pragma unroll
    for (int t = 0; t < LSEQ; t++) {
        const ulonglong2* hp = (const ulonglong2*)sh;
        unsigned long long a0 = 0ull, a1 = 0ull;
#pragma unroll
        for (int k = 0; k < 32; k++) {
            ulonglong2 hv = hp[k];
            FMA_F32X2(a0, wq[k].x, hv.x, a0);
            FMA_F32X2(a1, wq[k].y, hv.y, a1);
        }
        sgh[g] = unpack_sum(a0) + unpack_sum(a1) + bh;
        __syncthreads();   // gh ready; all reads of sh for step t done

        if (g < HDIM) {
            float ir = sgi[t][g], iz = sgi[t][g + 128], in_ = sgi[t][g + 256];
            float hr = sgh[g],    hz = sgh[g + 128],    hn  = sgh[g + 256];
            float r = 1.f / (1.f + expf(-(ir + hr)));
            float z = 1.f / (1.f + expf(-(iz + hz)));
            float n = tanhf(in_ + r * hn);
            hnew = (1.f - z) * n + z * sh[g];
            sh[g] = hnew;
        }
        __syncthreads();   // new h visible before next matvec
    }

    if (g < HDIM) g_enc[b * HDIM + g] = hnew;

    // --- last-CTA loss fusion ----------------------------------------------
    __threadfence();
    __syncthreads();
    if (tid == 0) s_amlast = (atomicAdd(&g_done, 1) == NB - 1);
    __syncthreads();
    if (!s_amlast) return;

    // This is the only CTA still alive; all of g_enc is globally visible.
    float4 nd = ((const float4*)g_enc)[lane];   // node = enc[0]

    float pos_acc = 0.f, neg_sum = 0.f;
    // 60 rows over 12 warps: warp w takes rows 1+w, 13+w, 25+w, 37+w, 49+w.
#pragma unroll
    for (int j = 0; j < 5; j++) {
        int i = 1 + w + 12 * j;
        float4 ev = ((const float4*)(g_enc + (size_t)i * HDIM))[lane];
        float p = nd.x * ev.x + nd.y * ev.y + nd.z * ev.z + nd.w * ev.w;
#pragma unroll
        for (int off = 16; off; off >>= 1)
            p += __shfl_xor_sync(0xffffffffu, p, off);
        float s = p * (1.0f / (float)HDIM);
        if (i <= NPOS) {
            pos_acc += s;
        } else if (s > 0.f) {
            neg_sum += expf(s);
        }
    }

    if (lane == 0) { sp[w] = pos_acc; sn[w] = neg_sum; }
    __syncthreads();
    if (tid == 0) {
        float P = 0.f, Ns = 0.f;
#pragma unroll
        for (int i = 0; i < 12; i++) { P += sp[i]; Ns += sn[i]; }
        // loss = -(neg_loss + pos_loss), neg_loss = -log(1 + neg_sum)
        out[0] = log1pf(Ns) - P;
        g_done = 0;   // reset for next graph replay (only this CTA is alive)
    }
}

// ---------------------------------------------------------------------------
extern "C" void kernel_launch(void* const* d_in, const int* in_sizes, int n_in,
                              void* d_out, int out_size)
{
    (void)in_sizes; (void)n_in; (void)out_size;
    enc_loss_kernel<<<NB, NG>>>(
        (const int*)d_in[0], (const int*)d_in[1], (const int*)d_in[2],
        (const float*)d_in[3], (const float*)d_in[4],
        (const float*)d_in[5], (const float*)d_in[6],
        (const float*)d_in[7], (const float*)d_in[8],
        (const float*)d_in[9], (float*)d_out);
}

// round 5
// speedup vs baseline: 1.2253x; 1.2228x over previous
#include <cuda_runtime.h>
#include <math.h>

#define EDIM 128
#define HDIM 128
#define LSEQ 10
#define NPOS 10
#define NNEG 50
#define NB   61
#define NG   384

#define CH_ROWS   48                  // rows staged per phase
#define CH_F4     (CH_ROWS * 32)      // 1536 float4 per phase
#define NPHASE    (NG / CH_ROWS)      // 8

// Packed f32x2 FMA (Blackwell): d = a*b + c elementwise on 2 packed floats.
#define FMA_F32X2(d, a, b, c) \
    asm("fma.rn.f32x2 %0, %1, %2, %3;" : "=l"(d) : "l"(a), "l"(b), "l"(c))

__device__ __forceinline__ float unpack_sum(unsigned long long v) {
    float lo, hi;
    asm("mov.b64 {%0, %1}, %2;" : "=f"(lo), "=f"(hi) : "l"(v));
    return lo + hi;
}

// Scratch: final hidden state per chain (61 x 128) + completion counter.
__device__ float g_enc[NB * HDIM];
__device__ int   g_done;   // zero-init; last CTA resets it after use

// Swizzled smem slot for float4-chunk c (0..CH_F4) of phase p.
__device__ __forceinline__ int sw_slot(int c, int p) {
    int lr = c >> 5;           // local row in phase
    int k  = c & 31;           // chunk within row
    int r  = p * CH_ROWS + lr; // global row
    return lr * 32 + ((k + r) & 31);
}

// Coalesced global->smem stage, then swizzled smem->register row reads.
// All NG threads participate; thread g ends with row g in wq[0..31].
__device__ __forceinline__ void stage_matrix(
    const float* __restrict__ W, ulonglong2* sbuf, ulonglong2 wq[32], int tid)
{
    const ulonglong2* Wq = (const ulonglong2*)W;
    ulonglong2 t0 = Wq[tid], t1 = Wq[tid + NG], t2 = Wq[tid + 2*NG], t3 = Wq[tid + 3*NG];
#pragma unroll
    for (int p = 0; p < NPHASE; p++) {
        sbuf[sw_slot(tid,          p)] = t0;
        sbuf[sw_slot(tid + NG,     p)] = t1;
        sbuf[sw_slot(tid + 2*NG,   p)] = t2;
        sbuf[sw_slot(tid + 3*NG,   p)] = t3;
        if (p < NPHASE - 1) {            // prefetch next phase (hides L2 latency)
            int base = (p + 1) * CH_F4 + tid;
            t0 = Wq[base]; t1 = Wq[base + NG]; t2 = Wq[base + 2*NG]; t3 = Wq[base + 3*NG];
        }
        __syncthreads();
        int lr = tid - p * CH_ROWS;
        if (lr >= 0 && lr < CH_ROWS) {
            int base = lr * 32;
#pragma unroll
            for (int k = 0; k < 32; k++)
                wq[k] = sbuf[base + ((k + tid) & 31)];
        }
        __syncthreads();
    }
}

// ---------------------------------------------------------------------------
// One CTA per chain; thread g owns weight row g register-resident (f32x2
// pairs), loaded via coalesced smem staging. Last CTA computes the loss.
// ---------------------------------------------------------------------------
__global__ __launch_bounds__(NG, 1) void enc_loss_kernel(
    const int* __restrict__ phr, const int* __restrict__ pos,
    const int* __restrict__ neg,
    const float* __restrict__ u_emb, const float* __restrict__ v_emb,
    const float* __restrict__ w_ih, const float* __restrict__ w_hh,
    const float* __restrict__ b_ih, const float* __restrict__ b_hh,
    const float* __restrict__ h0, float* __restrict__ out)
{
    __shared__ ulonglong2 sbuf[CH_F4];   // 24KB staging buffer
    __shared__ float sx[LSEQ][EDIM];     // gathered embeddings
    __shared__ float sgi[LSEQ][NG];      // input-projection gates
    __shared__ float sgh[NG];            // recurrent gates (per step)
    __shared__ float sh[HDIM];           // hidden state
    __shared__ int   s_amlast;
    __shared__ float sp[12], sn[12];

    const int b    = blockIdx.x;
    const int tid  = threadIdx.x;
    const int lane = tid & 31;
    const int w    = tid >> 5;

    // --- gather x[b] : 10 rows of 128 floats, float4-coalesced -------------
    if (tid < LSEQ * 32) {
        int t = tid >> 5, l = tid & 31;
        int idx;
        const float* table;
        if (b == 0)            { idx = phr[t];                         table = u_emb; }
        else if (b <= NPOS)    { idx = pos[(b - 1) * LSEQ + t];        table = v_emb; }
        else                   { idx = neg[(b - 1 - NPOS) * LSEQ + t]; table = v_emb; }
        const float4* src = (const float4*)(table + (size_t)idx * EDIM);
        ((float4*)&sx[t][0])[l] = src[l];
    }
    if (tid < HDIM) sh[tid] = h0[tid];

    const int g = tid;
    const float bi = b_ih[g];
    const float bh = b_hh[g];

    ulonglong2 wq[32];   // 128 floats as 64 packed f32x2 pairs

    // --- stage w_ih coalesced, then input projection ------------------------
    stage_matrix(w_ih, sbuf, wq, tid);   // barriers inside also cover sx/sh

#pragma unroll
    for (int t = 0; t < LSEQ; t++) {
        const ulonglong2* xp = (const ulonglong2*)&sx[t][0];
        unsigned long long a0 = 0ull, a1 = 0ull;
#pragma unroll
        for (int k = 0; k < 32; k++) {
            ulonglong2 xv = xp[k];
            FMA_F32X2(a0, wq[k].x, xv.x, a0);
            FMA_F32X2(a1, wq[k].y, xv.y, a1);
        }
        sgi[t][g] = unpack_sum(a0) + unpack_sum(a1) + bi;
    }

    // --- stage w_hh coalesced ----------------------------------------------
    stage_matrix(w_hh, sbuf, wq, tid);   // final barrier also covers sgi

    // --- recurrence ---------------------------------------------------------
    float hnew = 0.f;
#pragma unroll
    for (int t = 0; t < LSEQ; t++) {
        const ulonglong2* hp = (const ulonglong2*)sh;
        unsigned long long a0 = 0ull, a1 = 0ull;
#pragma unroll
        for (int k = 0; k < 32; k++) {
            ulonglong2 hv = hp[k];
            FMA_F32X2(a0, wq[k].x, hv.x, a0);
            FMA_F32X2(a1, wq[k].y, hv.y, a1);
        }
        sgh[g] = unpack_sum(a0) + unpack_sum(a1) + bh;
        __syncthreads();   // gh ready; all reads of sh for step t done

        if (g < HDIM) {
            float ir = sgi[t][g], iz = sgi[t][g + 128], in_ = sgi[t][g + 256];
            float hr = sgh[g],    hz = sgh[g + 128],    hn  = sgh[g + 256];
            float r = 1.f / (1.f + expf(-(ir + hr)));
            float z = 1.f / (1.f + expf(-(iz + hz)));
            float n = tanhf(in_ + r * hn);
            hnew = (1.f - z) * n + z * sh[g];
            sh[g] = hnew;
        }
        __syncthreads();   // new h visible before next matvec
    }

    if (g < HDIM) g_enc[b * HDIM + g] = hnew;

    // --- last-CTA loss fusion ----------------------------------------------
    __threadfence();
    __syncthreads();
    if (tid == 0) s_amlast = (atomicAdd(&g_done, 1) == NB - 1);
    __syncthreads();
    if (!s_amlast) return;

    float4 nd = ((const float4*)g_enc)[lane];   // node = enc[0]

    float pos_acc = 0.f, neg_sum = 0.f;
#pragma unroll
    for (int j = 0; j < 5; j++) {
        int i = 1 + w + 12 * j;
        float4 ev = ((const float4*)(g_enc + (size_t)i * HDIM))[lane];
        float p = nd.x * ev.x + nd.y * ev.y + nd.z * ev.z + nd.w * ev.w;
#pragma unroll
        for (int off = 16; off; off >>= 1)
            p += __shfl_xor_sync(0xffffffffu, p, off);
        float s = p * (1.0f / (float)HDIM);
        if (i <= NPOS) {
            pos_acc += s;
        } else if (s > 0.f) {
            neg_sum += expf(s);
        }
    }

    if (lane == 0) { sp[w] = pos_acc; sn[w] = neg_sum; }
    __syncthreads();
    if (tid == 0) {
        float P = 0.f, Ns = 0.f;
#pragma unroll
        for (int i = 0; i < 12; i++) { P += sp[i]; Ns += sn[i]; }
        out[0] = log1pf(Ns) - P;   // loss = log(1+neg_sum) - pos_loss
        g_done = 0;                // reset for next graph replay
    }
}

// ---------------------------------------------------------------------------
extern "C" void kernel_launch(void* const* d_in, const int* in_sizes, int n_in,
                              void* d_out, int out_size)
{
    (void)in_sizes; (void)n_in; (void)out_size;
    enc_loss_kernel<<<NB, NG>>>(
        (const int*)d_in[0], (const int*)d_in[1], (const int*)d_in[2],
        (const float*)d_in[3], (const float*)d_in[4],
        (const float*)d_in[5], (const float*)d_in[6],
        (const float*)d_in[7], (const float*)d_in[8],
        (const float*)d_in[9], (float*)d_out);
}